// round 6
// baseline (speedup 1.0000x reference)
#include <cuda_runtime.h>
#include <cstdint>

#define M_TOTAL 32768
#define E_DIM 2048
#define L_DIM 64
#define H_DIM 128
#define S_LEN 4096

// Scratch (device globals: allocation-free rule)
__device__ float g_q[(size_t)M_TOTAL * H_DIM];
__device__ float g_k[(size_t)M_TOTAL * H_DIM];
__device__ float g_v[(size_t)M_TOTAL * H_DIM];

// Pre-rounded (tf32-rna) weights, same layouts as inputs:
// [w_dkv (2048x64) | w_q (2048x128) | w_k (64x128) | w_v (64x128)]
#define WR_DKV 0
#define WR_Q   (2048 * 64)
#define WR_K   (WR_Q + 2048 * 128)
#define WR_V   (WR_K + 64 * 128)
#define WR_TOT (WR_V + 64 * 128)
__device__ float g_wr[WR_TOT];

// ---------------- tf32 / async helpers ----------------

__device__ __forceinline__ void mma_tf32(float* d, const uint32_t* a, const uint32_t* b) {
    asm volatile(
        "mma.sync.aligned.m16n8k8.row.col.f32.tf32.tf32.f32 "
        "{%0,%1,%2,%3}, {%4,%5,%6,%7}, {%8,%9}, {%0,%1,%2,%3};\n"
        : "+f"(d[0]), "+f"(d[1]), "+f"(d[2]), "+f"(d[3])
        : "r"(a[0]), "r"(a[1]), "r"(a[2]), "r"(a[3]), "r"(b[0]), "r"(b[1]));
}

__device__ __forceinline__ uint32_t to_tf32(float x) {
    uint32_t h;
    asm("cvt.rna.tf32.f32 %0, %1;" : "=r"(h) : "f"(x));
    return h;
}

__device__ __forceinline__ void split_tf32(float x, uint32_t& hi, uint32_t& lo) {
    uint32_t h = to_tf32(x);
    hi = h;
    lo = __float_as_uint(x - __uint_as_float(h));
}

__device__ __forceinline__ void cp16(void* dst, const void* src) {
    uint32_t d = (uint32_t)__cvta_generic_to_shared(dst);
    asm volatile("cp.async.cg.shared.global [%0], [%1], 16;\n" :: "r"(d), "l"(src));
}
#define CP_COMMIT asm volatile("cp.async.commit_group;\n")
#define CP_WAIT0  asm volatile("cp.async.wait_group 0;\n")
#define CP_WAIT1  asm volatile("cp.async.wait_group 1;\n")
#define CP_WAIT2  asm volatile("cp.async.wait_group 2;\n")

// ---------------- weight pre-rounding (once per call, ~5us) ----------------

__global__ void prep_w(const float* __restrict__ w_dkv, const float* __restrict__ w_q,
                       const float* __restrict__ w_k, const float* __restrict__ w_v) {
    int i = blockIdx.x * 256 + threadIdx.x;
    float v;
    if (i < WR_Q)       v = w_dkv[i];
    else if (i < WR_K)  v = w_q[i - WR_Q];
    else if (i < WR_V)  v = w_k[i - WR_K];
    else                v = w_v[i - WR_V];
    g_wr[i] = __uint_as_float(to_tf32(v));
}

// ---------------- 3-stage pipelined 2xTF32 GEMM ----------------
// C = A[M,K] @ concat(B1[K,N1], B2[K,N2]); B pre-rounded tf32; A split hi/lo.
// BM=64, KT=32, 256 threads = 8 warps as 2(m) x 4(n). round_c: rna-round outputs.

template <int BN>
__global__ void __launch_bounds__(256, 2) gemm_kernel(
    const float* __restrict__ A,
    const float* __restrict__ B1, const float* __restrict__ B2,
    float* __restrict__ C1, float* __restrict__ C2,
    int K, int N1, int N2, int round_c)
{
    constexpr int BM = 64;
    constexpr int KTL = 32;
    constexpr int WNT = BN / 32;
    constexpr int ASTR = KTL + 4;           // 36
    constexpr int BSTR = BN + 8;
    constexpr int ASZ = BM * ASTR;
    constexpr int BSZ = KTL * BSTR;
    constexpr int BUF = ASZ + BSZ;

    extern __shared__ float sh[];

    const int tid = threadIdx.x;
    const int warp = tid >> 5, lane = tid & 31;
    const int wm = warp >> 2;
    const int wn = warp & 3;
    const int lr = lane >> 2, lc = lane & 3;
    const int m0 = blockIdx.x * BM;
    const int n0 = blockIdx.y * BN;

    const int arow = tid >> 2;              // 0..63
    const int ac4 = (tid & 3) * 4;          // 0,4,8,12 (+16)

    float acc[2][WNT][4];
#pragma unroll
    for (int mt = 0; mt < 2; mt++)
#pragma unroll
        for (int nt = 0; nt < WNT; nt++)
#pragma unroll
            for (int j = 0; j < 4; j++) acc[mt][nt][j] = 0.f;

    const int nk = K / KTL;

    auto stage = [&](int kt) {
        float* As = sh + (kt % 3) * BUF;
        float* Bs = As + ASZ;
        int kb = kt * KTL;
        cp16(&As[arow * ASTR + ac4],      A + (size_t)(m0 + arow) * K + kb + ac4);
        cp16(&As[arow * ASTR + ac4 + 16], A + (size_t)(m0 + arow) * K + kb + ac4 + 16);
        constexpr int NB = (KTL * BN / 4) / 256;
#pragma unroll
        for (int it = 0; it < NB; it++) {
            int i = it * 256 + tid;
            int brow = i / (BN / 4);
            int bc4 = (i % (BN / 4)) * 4;
            int gc = n0 + bc4;
            const float* src = (gc < N1) ? (B1 + (size_t)(kb + brow) * N1 + gc)
                                         : (B2 + (size_t)(kb + brow) * N2 + (gc - N1));
            cp16(&Bs[brow * BSTR + bc4], src);
        }
        CP_COMMIT;
    };

    // prologue: stage tiles 0 and 1
    stage(0);
    if (nk > 1) stage(1);

    for (int kt = 0; kt < nk; kt++) {
        if (kt + 2 < nk) { stage(kt + 2); CP_WAIT2; }
        else if (kt + 1 < nk) CP_WAIT1;
        else CP_WAIT0;
        __syncthreads();

        const float* As = sh + (kt % 3) * BUF;
        const float* Bs = As + ASZ;

#pragma unroll
        for (int ks = 0; ks < 4; ks++) {
            uint32_t ah[2][4], al[2][4];
#pragma unroll
            for (int mt = 0; mt < 2; mt++) {
                int rb = wm * 32 + mt * 16;
                split_tf32(As[(rb + lr) * ASTR + ks * 8 + lc],         ah[mt][0], al[mt][0]);
                split_tf32(As[(rb + lr + 8) * ASTR + ks * 8 + lc],     ah[mt][1], al[mt][1]);
                split_tf32(As[(rb + lr) * ASTR + ks * 8 + lc + 4],     ah[mt][2], al[mt][2]);
                split_tf32(As[(rb + lr + 8) * ASTR + ks * 8 + lc + 4], ah[mt][3], al[mt][3]);
            }
#pragma unroll
            for (int nt = 0; nt < WNT; nt++) {
                int c0 = wn * (BN / 4) + nt * 8 + lr;
                uint32_t bh[2];
                bh[0] = __float_as_uint(Bs[(ks * 8 + lc) * BSTR + c0]);
                bh[1] = __float_as_uint(Bs[(ks * 8 + lc + 4) * BSTR + c0]);
#pragma unroll
                for (int mt = 0; mt < 2; mt++) {
                    mma_tf32(acc[mt][nt], ah[mt], bh);
                    mma_tf32(acc[mt][nt], al[mt], bh);
                }
            }
        }
        __syncthreads();
    }

    // Store (optionally rna-rounded: k/v so attention's HW truncation is exact)
#pragma unroll
    for (int mt = 0; mt < 2; mt++) {
        int r0 = m0 + wm * 32 + mt * 16 + lr;
#pragma unroll
        for (int nt = 0; nt < WNT; nt++) {
            int gc = n0 + wn * (BN / 4) + nt * 8 + lc * 2;
            float* dst;
            int stride, col;
            if (gc < N1) { dst = C1; stride = N1; col = gc; }
            else         { dst = C2; stride = N2; col = gc - N1; }
            float o0 = acc[mt][nt][0], o1 = acc[mt][nt][1];
            float o2 = acc[mt][nt][2], o3 = acc[mt][nt][3];
            if (round_c) {
                o0 = __uint_as_float(to_tf32(o0));
                o1 = __uint_as_float(to_tf32(o1));
                o2 = __uint_as_float(to_tf32(o2));
                o3 = __uint_as_float(to_tf32(o3));
            }
            *(float2*)(dst + (size_t)r0 * stride + col)       = make_float2(o0, o1);
            *(float2*)(dst + (size_t)(r0 + 8) * stride + col) = make_float2(o2, o3);
        }
    }
}

// ---------------- Flash attention (causal) ----------------
// BLOCK_M=128 (8 warps x 16 rows), BLOCK_N=64, HEAD=128, 256 threads, 1 CTA/SM.
// Double-buffered K/V via cp.async (load t+1 overlaps compute t).
// QK^T: 2xTF32 (q split on the fly; K tf32-rna from gemm2). PV: 1xTF32.

constexpr int AKS = 132;   // K row stride
constexpr int AVS = 136;   // V row stride
constexpr int APS = 68;    // P row stride
constexpr int KS_SZ = 64 * AKS;
constexpr int VS_SZ = 64 * AVS;
constexpr int VOFF = 2 * KS_SZ;
constexpr int POFF = VOFF + 2 * VS_SZ;
constexpr int ATTN_SMEM_BYTES = (POFF + 8 * 16 * APS) * 4;   // 172032

__global__ void __launch_bounds__(256, 1) attn_kernel(
    const float* __restrict__ q, const float* __restrict__ k,
    const float* __restrict__ v, float* __restrict__ out)
{
    extern __shared__ float sm[];

    const int idx = blockIdx.x;
    const int b = idx & 7;
    const int qb = 31 - (idx >> 3);         // longest first
    const int tid = threadIdx.x;
    const int warp = tid >> 5, lane = tid & 31;   // 8 warps x 16 rows
    const int lr = lane >> 2, lc = lane & 3;

    const float* qB = q + (size_t)b * S_LEN * H_DIM;
    const float* kB = k + (size_t)b * S_LEN * H_DIM;
    const float* vB = v + (size_t)b * S_LEN * H_DIM;

    const int qrow0 = qb * 128 + warp * 16 + lr;
    const float SCALE = 0.08838834764831845f;  // 1/sqrt(128)

    // q fragments in registers (fp32; split hi/lo on the fly)
    float qreg[64];
#pragma unroll
    for (int ks = 0; ks < 16; ks++) {
        int c = ks * 8 + lc;
        qreg[ks * 4 + 0] = qB[(size_t)qrow0 * H_DIM + c] * SCALE;
        qreg[ks * 4 + 1] = qB[(size_t)(qrow0 + 8) * H_DIM + c] * SCALE;
        qreg[ks * 4 + 2] = qB[(size_t)qrow0 * H_DIM + c + 4] * SCALE;
        qreg[ks * 4 + 3] = qB[(size_t)(qrow0 + 8) * H_DIM + c + 4] * SCALE;
    }

    float acc[16][4];
#pragma unroll
    for (int nt = 0; nt < 16; nt++)
#pragma unroll
        for (int j = 0; j < 4; j++) acc[nt][j] = 0.f;
    float mrow[2] = {-INFINITY, -INFINITY};
    float lrow[2] = {0.f, 0.f};

    // loader mapping: 4 threads per kv row, each loads 32 cols (8 cp16)
    const int krow = tid >> 2;              // 0..63
    const int kcb = (tid & 3) * 32;

    const int ntkv = 2 * qb + 2;

    auto load_tile = [&](int t, int buf) {
        const float* ksrc = kB + (size_t)(t * 64 + krow) * H_DIM + kcb;
        const float* vsrc = vB + (size_t)(t * 64 + krow) * H_DIM + kcb;
        float* kd = sm + buf * KS_SZ + krow * AKS + kcb;
        float* vd = sm + VOFF + buf * VS_SZ + krow * AVS + kcb;
#pragma unroll
        for (int i = 0; i < 8; i++) cp16(kd + i * 4, ksrc + i * 4);
#pragma unroll
        for (int i = 0; i < 8; i++) cp16(vd + i * 4, vsrc + i * 4);
        CP_COMMIT;
    };

    load_tile(0, 0);

    for (int t = 0; t < ntkv; t++) {
        if (t + 1 < ntkv) { load_tile(t + 1, (t + 1) & 1); CP_WAIT1; }
        else CP_WAIT0;
        __syncthreads();

        const float* Ks = sm + (t & 1) * KS_SZ;
        const float* Vs = sm + VOFF + (t & 1) * VS_SZ;

        // ---- S = q @ k^T (2xTF32) ----
        float sc[8][4];
#pragma unroll
        for (int nt = 0; nt < 8; nt++)
#pragma unroll
            for (int j = 0; j < 4; j++) sc[nt][j] = 0.f;

#pragma unroll
        for (int ks = 0; ks < 16; ks++) {
            uint32_t ah[4], al[4];
#pragma unroll
            for (int j = 0; j < 4; j++) split_tf32(qreg[ks * 4 + j], ah[j], al[j]);
#pragma unroll
            for (int nt = 0; nt < 8; nt++) {
                uint32_t bh[2];
                bh[0] = __float_as_uint(Ks[(nt * 8 + lr) * AKS + ks * 8 + lc]);
                bh[1] = __float_as_uint(Ks[(nt * 8 + lr) * AKS + ks * 8 + lc + 4]);
                mma_tf32(sc[nt], ah, bh);
                mma_tf32(sc[nt], al, bh);
            }
        }

        // Causal mask on boundary tiles
        if (t >= 2 * qb) {
#pragma unroll
            for (int nt = 0; nt < 8; nt++)
#pragma unroll
                for (int j = 0; j < 4; j++) {
                    int col = t * 64 + nt * 8 + lc * 2 + (j & 1);
                    int row = qb * 128 + warp * 16 + lr + (j >> 1) * 8;
                    if (col > row) sc[nt][j] = -INFINITY;
                }
        }

        // ---- online softmax ----
        float mnew[2] = {-INFINITY, -INFINITY};
#pragma unroll
        for (int nt = 0; nt < 8; nt++)
#pragma unroll
            for (int j = 0; j < 4; j++) mnew[j >> 1] = fmaxf(mnew[j >> 1], sc[nt][j]);
#pragma unroll
        for (int off = 1; off < 4; off <<= 1) {
            mnew[0] = fmaxf(mnew[0], __shfl_xor_sync(0xffffffffu, mnew[0], off));
            mnew[1] = fmaxf(mnew[1], __shfl_xor_sync(0xffffffffu, mnew[1], off));
        }
        float mtot0 = fmaxf(mrow[0], mnew[0]);
        float mtot1 = fmaxf(mrow[1], mnew[1]);
        float alpha0 = __expf(mrow[0] - mtot0);
        float alpha1 = __expf(mrow[1] - mtot1);
        mrow[0] = mtot0; mrow[1] = mtot1;

        float rs[2] = {0.f, 0.f};
#pragma unroll
        for (int nt = 0; nt < 8; nt++)
#pragma unroll
            for (int j = 0; j < 4; j++) {
                float p = __expf(sc[nt][j] - ((j >> 1) ? mtot1 : mtot0));
                sc[nt][j] = p;
                rs[j >> 1] += p;
            }
#pragma unroll
        for (int off = 1; off < 4; off <<= 1) {
            rs[0] += __shfl_xor_sync(0xffffffffu, rs[0], off);
            rs[1] += __shfl_xor_sync(0xffffffffu, rs[1], off);
        }
        lrow[0] = lrow[0] * alpha0 + rs[0];
        lrow[1] = lrow[1] * alpha1 + rs[1];

#pragma unroll
        for (int nt = 0; nt < 16; nt++) {
            acc[nt][0] *= alpha0; acc[nt][1] *= alpha0;
            acc[nt][2] *= alpha1; acc[nt][3] *= alpha1;
        }

        // P -> smem (per-warp private), rna-rounded
        float* Pw = sm + POFF + warp * 16 * APS;
#pragma unroll
        for (int nt = 0; nt < 8; nt++)
#pragma unroll
            for (int j = 0; j < 4; j++) {
                int row = lr + (j >> 1) * 8;
                int col = nt * 8 + lc * 2 + (j & 1);
                Pw[row * APS + col] = __uint_as_float(to_tf32(sc[nt][j]));
            }
        __syncwarp();

        // ---- O += P @ V (1xTF32) ----
#pragma unroll
        for (int ks2 = 0; ks2 < 8; ks2++) {
            uint32_t pa[4];
            pa[0] = __float_as_uint(Pw[lr * APS + ks2 * 8 + lc]);
            pa[1] = __float_as_uint(Pw[(lr + 8) * APS + ks2 * 8 + lc]);
            pa[2] = __float_as_uint(Pw[lr * APS + ks2 * 8 + lc + 4]);
            pa[3] = __float_as_uint(Pw[(lr + 8) * APS + ks2 * 8 + lc + 4]);
#pragma unroll
            for (int nt2 = 0; nt2 < 16; nt2++) {
                uint32_t vb[2];
                vb[0] = __float_as_uint(Vs[(ks2 * 8 + lc) * AVS + nt2 * 8 + lr]);
                vb[1] = __float_as_uint(Vs[(ks2 * 8 + lc + 4) * AVS + nt2 * 8 + lr]);
                mma_tf32(acc[nt2], pa, vb);
            }
        }
        __syncthreads();  // all warps done with this buffer before next prefetch overwrites
    }

    // Epilogue
    float inv0 = 1.f / lrow[0];
    float inv1 = 1.f / lrow[1];
    size_t obase = ((size_t)b * S_LEN + qrow0) * H_DIM;
#pragma unroll
    for (int nt2 = 0; nt2 < 16; nt2++) {
        int col = nt2 * 8 + lc * 2;
        *(float2*)(out + obase + col) =
            make_float2(acc[nt2][0] * inv0, acc[nt2][1] * inv0);
        *(float2*)(out + obase + (size_t)8 * H_DIM + col) =
            make_float2(acc[nt2][2] * inv1, acc[nt2][3] * inv1);
    }
}

// ---------------- launch ----------------

extern "C" void kernel_launch(void* const* d_in, const int* in_sizes, int n_in,
                              void* d_out, int out_size) {
    const float* x     = (const float*)d_in[0];
    const float* w_dkv = (const float*)d_in[1];
    const float* w_k   = (const float*)d_in[2];
    const float* w_v   = (const float*)d_in[3];
    const float* w_q   = (const float*)d_in[4];

    float* out = (float*)d_out;                          // [B,S,HEAD]
    float* latent = out + (size_t)M_TOTAL * H_DIM;       // [B,S,LATENT]

    float *qp, *kp, *vp, *wr;
    cudaGetSymbolAddress((void**)&qp, g_q);
    cudaGetSymbolAddress((void**)&kp, g_k);
    cudaGetSymbolAddress((void**)&vp, g_v);
    cudaGetSymbolAddress((void**)&wr, g_wr);

    constexpr int SMEM1 = 3 * (64 * 36 + 32 * (192 + 8)) * 4;  // 104448
    constexpr int SMEM2 = 3 * (64 * 36 + 32 * (64 + 8)) * 4;   // 55296

    static bool attrs_set = false;
    if (!attrs_set) {
        cudaFuncSetAttribute(gemm_kernel<192>,
                             cudaFuncAttributeMaxDynamicSharedMemorySize, SMEM1);
        cudaFuncSetAttribute(gemm_kernel<64>,
                             cudaFuncAttributeMaxDynamicSharedMemorySize, SMEM2);
        cudaFuncSetAttribute(attn_kernel,
                             cudaFuncAttributeMaxDynamicSharedMemorySize, ATTN_SMEM_BYTES);
        attrs_set = true;
    }

    // 0) pre-round all weights to tf32-rna (unbiased)
    prep_w<<<WR_TOT / 256, 256>>>(w_dkv, w_q, w_k, w_v);

    // 1) latent = x@w_dkv -> d_out latent region; q = x@w_q -> scratch (fp32 out)
    gemm_kernel<192><<<dim3(M_TOTAL / 64, 1), 256, SMEM1>>>(
        x, wr + WR_DKV, wr + WR_Q, latent, qp, E_DIM, L_DIM, H_DIM, 0);

    // 2) k = latent@w_k, v = latent@w_v -> scratch, rna-rounded on store
    gemm_kernel<64><<<dim3(M_TOTAL / 64, 4), 256, SMEM2>>>(
        latent, wr + WR_K, wr + WR_V, kp, vp, L_DIM, H_DIM, H_DIM, 1);

    // 3) causal flash attention (BLOCK_M=128, double-buffered K/V)
    attn_kernel<<<256, 256, ATTN_SMEM_BYTES>>>(qp, kp, vp, out);
}

// round 7
// speedup vs baseline: 1.1504x; 1.1504x over previous
#include <cuda_runtime.h>
#include <cstdint>

#define M_TOTAL 32768
#define E_DIM 2048
#define L_DIM 64
#define H_DIM 128
#define S_LEN 4096

// Scratch (device globals: allocation-free rule)
__device__ float g_q[(size_t)M_TOTAL * H_DIM];
__device__ float g_k[(size_t)M_TOTAL * H_DIM];
__device__ float g_v[(size_t)M_TOTAL * H_DIM];

// Pre-rounded (tf32-rna) weights, same layouts as inputs:
// [w_dkv (2048x64) | w_q (2048x128) | w_k (64x128) | w_v (64x128)]
#define WR_DKV 0
#define WR_Q   (2048 * 64)
#define WR_K   (WR_Q + 2048 * 128)
#define WR_V   (WR_K + 64 * 128)
#define WR_TOT (WR_V + 64 * 128)
__device__ float g_wr[WR_TOT];

// ---------------- tf32 / async helpers ----------------

__device__ __forceinline__ void mma_tf32(float* d, const uint32_t* a, const uint32_t* b) {
    asm volatile(
        "mma.sync.aligned.m16n8k8.row.col.f32.tf32.tf32.f32 "
        "{%0,%1,%2,%3}, {%4,%5,%6,%7}, {%8,%9}, {%0,%1,%2,%3};\n"
        : "+f"(d[0]), "+f"(d[1]), "+f"(d[2]), "+f"(d[3])
        : "r"(a[0]), "r"(a[1]), "r"(a[2]), "r"(a[3]), "r"(b[0]), "r"(b[1]));
}

__device__ __forceinline__ uint32_t to_tf32(float x) {
    uint32_t h;
    asm("cvt.rna.tf32.f32 %0, %1;" : "=r"(h) : "f"(x));
    return h;
}

__device__ __forceinline__ void split_tf32(float x, uint32_t& hi, uint32_t& lo) {
    uint32_t h = to_tf32(x);
    hi = h;
    lo = __float_as_uint(x - __uint_as_float(h));
}

__device__ __forceinline__ void cp16(void* dst, const void* src) {
    uint32_t d = (uint32_t)__cvta_generic_to_shared(dst);
    asm volatile("cp.async.cg.shared.global [%0], [%1], 16;\n" :: "r"(d), "l"(src));
}
#define CP_COMMIT asm volatile("cp.async.commit_group;\n")
#define CP_WAIT0  asm volatile("cp.async.wait_group 0;\n")
#define CP_WAIT1  asm volatile("cp.async.wait_group 1;\n")
#define CP_WAIT2  asm volatile("cp.async.wait_group 2;\n")

// ---------------- weight pre-rounding (once per call, ~5us) ----------------

__global__ void prep_w(const float* __restrict__ w_dkv, const float* __restrict__ w_q,
                       const float* __restrict__ w_k, const float* __restrict__ w_v) {
    int i = blockIdx.x * 256 + threadIdx.x;
    float v;
    if (i < WR_Q)       v = w_dkv[i];
    else if (i < WR_K)  v = w_q[i - WR_Q];
    else if (i < WR_V)  v = w_k[i - WR_K];
    else                v = w_v[i - WR_V];
    g_wr[i] = __uint_as_float(to_tf32(v));
}

// ---------------- 3-stage pipelined 2xTF32 GEMM ----------------
// C = A[M,K] @ concat(B1[K,N1], B2[K,N2]); B pre-rounded tf32; A split hi/lo.
// BM=64, KT=32, 256 threads = 8 warps as 2(m) x 4(n), 3 CTAs/SM.
// Grid: (n-blocks, m-blocks) so n-blocks sharing an A tile are adjacent bids.

template <int BN>
__global__ void __launch_bounds__(256, 3) gemm_kernel(
    const float* __restrict__ A,
    const float* __restrict__ B1, const float* __restrict__ B2,
    float* __restrict__ C1, float* __restrict__ C2,
    int K, int N1, int N2, int round_c)
{
    constexpr int BM = 64;
    constexpr int KTL = 32;
    constexpr int WNT = BN / 32;
    constexpr int ASTR = KTL + 4;           // 36
    constexpr int BSTR = BN + 8;
    constexpr int ASZ = BM * ASTR;
    constexpr int BSZ = KTL * BSTR;
    constexpr int BUF = ASZ + BSZ;

    extern __shared__ float sh[];

    const int tid = threadIdx.x;
    const int warp = tid >> 5, lane = tid & 31;
    const int wm = warp >> 2;
    const int wn = warp & 3;
    const int lr = lane >> 2, lc = lane & 3;
    const int m0 = blockIdx.y * BM;
    const int n0 = blockIdx.x * BN;

    const int arow = tid >> 2;              // 0..63
    const int ac4 = (tid & 3) * 4;          // 0,4,8,12 (+16)

    float acc[2][WNT][4];
#pragma unroll
    for (int mt = 0; mt < 2; mt++)
#pragma unroll
        for (int nt = 0; nt < WNT; nt++)
#pragma unroll
            for (int j = 0; j < 4; j++) acc[mt][nt][j] = 0.f;

    const int nk = K / KTL;

    auto stage = [&](int kt) {
        float* As = sh + (kt % 3) * BUF;
        float* Bs = As + ASZ;
        int kb = kt * KTL;
        cp16(&As[arow * ASTR + ac4],      A + (size_t)(m0 + arow) * K + kb + ac4);
        cp16(&As[arow * ASTR + ac4 + 16], A + (size_t)(m0 + arow) * K + kb + ac4 + 16);
        constexpr int NB = (KTL * BN / 4) / 256;
#pragma unroll
        for (int it = 0; it < NB; it++) {
            int i = it * 256 + tid;
            int brow = i / (BN / 4);
            int bc4 = (i % (BN / 4)) * 4;
            int gc = n0 + bc4;
            const float* src = (gc < N1) ? (B1 + (size_t)(kb + brow) * N1 + gc)
                                         : (B2 + (size_t)(kb + brow) * N2 + (gc - N1));
            cp16(&Bs[brow * BSTR + bc4], src);
        }
        CP_COMMIT;
    };

    stage(0);
    if (nk > 1) stage(1);

    for (int kt = 0; kt < nk; kt++) {
        if (kt + 2 < nk) { stage(kt + 2); CP_WAIT2; }
        else if (kt + 1 < nk) CP_WAIT1;
        else CP_WAIT0;
        __syncthreads();

        const float* As = sh + (kt % 3) * BUF;
        const float* Bs = As + ASZ;

#pragma unroll
        for (int ks = 0; ks < 4; ks++) {
            uint32_t ah[2][4], al[2][4];
#pragma unroll
            for (int mt = 0; mt < 2; mt++) {
                int rb = wm * 32 + mt * 16;
                split_tf32(As[(rb + lr) * ASTR + ks * 8 + lc],         ah[mt][0], al[mt][0]);
                split_tf32(As[(rb + lr + 8) * ASTR + ks * 8 + lc],     ah[mt][1], al[mt][1]);
                split_tf32(As[(rb + lr) * ASTR + ks * 8 + lc + 4],     ah[mt][2], al[mt][2]);
                split_tf32(As[(rb + lr + 8) * ASTR + ks * 8 + lc + 4], ah[mt][3], al[mt][3]);
            }
#pragma unroll
            for (int nt = 0; nt < WNT; nt++) {
                int c0 = wn * (BN / 4) + nt * 8 + lr;
                uint32_t bh[2];
                bh[0] = __float_as_uint(Bs[(ks * 8 + lc) * BSTR + c0]);
                bh[1] = __float_as_uint(Bs[(ks * 8 + lc + 4) * BSTR + c0]);
#pragma unroll
                for (int mt = 0; mt < 2; mt++) {
                    mma_tf32(acc[mt][nt], ah[mt], bh);
                    mma_tf32(acc[mt][nt], al[mt], bh);
                }
            }
        }
        __syncthreads();
    }

    // Store (optionally rna-rounded: k/v so attention's HW truncation is exact)
#pragma unroll
    for (int mt = 0; mt < 2; mt++) {
        int r0 = m0 + wm * 32 + mt * 16 + lr;
#pragma unroll
        for (int nt = 0; nt < WNT; nt++) {
            int gc = n0 + wn * (BN / 4) + nt * 8 + lc * 2;
            float* dst;
            int stride, col;
            if (gc < N1) { dst = C1; stride = N1; col = gc; }
            else         { dst = C2; stride = N2; col = gc - N1; }
            float o0 = acc[mt][nt][0], o1 = acc[mt][nt][1];
            float o2 = acc[mt][nt][2], o3 = acc[mt][nt][3];
            if (round_c) {
                o0 = __uint_as_float(to_tf32(o0));
                o1 = __uint_as_float(to_tf32(o1));
                o2 = __uint_as_float(to_tf32(o2));
                o3 = __uint_as_float(to_tf32(o3));
            }
            *(float2*)(dst + (size_t)r0 * stride + col)       = make_float2(o0, o1);
            *(float2*)(dst + (size_t)(r0 + 8) * stride + col) = make_float2(o2, o3);
        }
    }
}

// ---------------- Flash attention (causal) ----------------
// BLOCK_M=64 (4 warps x 16 rows), BLOCK_N=64, HEAD=128, 128 threads, 2 CTA/SM.
// Softmax in exp2 domain (log2e folded into scale). QK^T: 2xTF32 (q split
// on the fly; K tf32-rna from gemm2). PV: 1xTF32 (P rna; V tf32-rna).

constexpr int AKS = 132;
constexpr int AVS = 136;
constexpr int APS = 68;
constexpr int ATTN_SMEM_BYTES = (64 * AKS + 64 * AVS + 64 * APS) * 4;  // 86016

__global__ void __launch_bounds__(128, 2) attn_kernel(
    const float* __restrict__ q, const float* __restrict__ k,
    const float* __restrict__ v, float* __restrict__ out)
{
    extern __shared__ float sm[];
    float* Ks = sm;
    float* Vs = sm + 64 * AKS;
    float* Ps = Vs + 64 * AVS;

    const int idx = blockIdx.x;
    const int b = idx & 7;
    const int qb = 63 - (idx >> 3);         // longest first
    const int tid = threadIdx.x;
    const int warp = tid >> 5, lane = tid & 31;
    const int lr = lane >> 2, lc = lane & 3;

    const float* qB = q + (size_t)b * S_LEN * H_DIM;
    const float* kB = k + (size_t)b * S_LEN * H_DIM;
    const float* vB = v + (size_t)b * S_LEN * H_DIM;

    const int qrow0 = qb * 64 + warp * 16 + lr;
    // 1/sqrt(128) * log2(e): scores in log2 domain -> exp2 softmax
    const float SCALE = 0.08838834764831845f * 1.4426950408889634f;

    // q fragments in registers (fp32; split hi/lo on the fly)
    float qreg[64];
#pragma unroll
    for (int ks = 0; ks < 16; ks++) {
        int c = ks * 8 + lc;
        qreg[ks * 4 + 0] = qB[(size_t)qrow0 * H_DIM + c] * SCALE;
        qreg[ks * 4 + 1] = qB[(size_t)(qrow0 + 8) * H_DIM + c] * SCALE;
        qreg[ks * 4 + 2] = qB[(size_t)qrow0 * H_DIM + c + 4] * SCALE;
        qreg[ks * 4 + 3] = qB[(size_t)(qrow0 + 8) * H_DIM + c + 4] * SCALE;
    }

    float acc[16][4];
#pragma unroll
    for (int nt = 0; nt < 16; nt++)
#pragma unroll
        for (int j = 0; j < 4; j++) acc[nt][j] = 0.f;
    float mrow[2] = {-INFINITY, -INFINITY};
    float lrow[2] = {0.f, 0.f};

    const int row64 = tid >> 5;
    const int c4 = (tid & 31) * 4;

    for (int kv = 0; kv <= qb; kv++) {
        __syncthreads();  // previous tile's readers done before overwrite

        // cp.async K,V tiles (64x128 each); values already tf32-rna from gemm2
#pragma unroll
        for (int rnd = 0; rnd < 16; rnd++) {
            int row = row64 + rnd * 4;
            cp16(&Ks[row * AKS + c4], kB + (size_t)(kv * 64 + row) * H_DIM + c4);
            cp16(&Vs[row * AVS + c4], vB + (size_t)(kv * 64 + row) * H_DIM + c4);
        }
        CP_COMMIT;
        CP_WAIT0;
        __syncthreads();

        // ---- S = q @ k^T (2xTF32) ----
        float sc[8][4];
#pragma unroll
        for (int nt = 0; nt < 8; nt++)
#pragma unroll
            for (int j = 0; j < 4; j++) sc[nt][j] = 0.f;

#pragma unroll
        for (int ks = 0; ks < 16; ks++) {
            uint32_t ah[4], al[4];
#pragma unroll
            for (int j = 0; j < 4; j++) split_tf32(qreg[ks * 4 + j], ah[j], al[j]);
#pragma unroll
            for (int nt = 0; nt < 8; nt++) {
                uint32_t bh[2];
                bh[0] = __float_as_uint(Ks[(nt * 8 + lr) * AKS + ks * 8 + lc]);
                bh[1] = __float_as_uint(Ks[(nt * 8 + lr) * AKS + ks * 8 + lc + 4]);
                mma_tf32(sc[nt], ah, bh);
                mma_tf32(sc[nt], al, bh);
            }
        }

        // Diagonal-block causal mask
        if (kv == qb) {
#pragma unroll
            for (int nt = 0; nt < 8; nt++)
#pragma unroll
                for (int j = 0; j < 4; j++) {
                    int col = nt * 8 + lc * 2 + (j & 1);
                    int row = warp * 16 + lr + (j >> 1) * 8;
                    if (col > row) sc[nt][j] = -INFINITY;
                }
        }

        // ---- online softmax (exp2 domain) ----
        float mnew[2] = {-INFINITY, -INFINITY};
#pragma unroll
        for (int nt = 0; nt < 8; nt++)
#pragma unroll
            for (int j = 0; j < 4; j++) mnew[j >> 1] = fmaxf(mnew[j >> 1], sc[nt][j]);
#pragma unroll
        for (int off = 1; off < 4; off <<= 1) {
            mnew[0] = fmaxf(mnew[0], __shfl_xor_sync(0xffffffffu, mnew[0], off));
            mnew[1] = fmaxf(mnew[1], __shfl_xor_sync(0xffffffffu, mnew[1], off));
        }
        float mtot0 = fmaxf(mrow[0], mnew[0]);
        float mtot1 = fmaxf(mrow[1], mnew[1]);
        float alpha0 = exp2f(mrow[0] - mtot0);
        float alpha1 = exp2f(mrow[1] - mtot1);
        mrow[0] = mtot0; mrow[1] = mtot1;

        float rs[2] = {0.f, 0.f};
#pragma unroll
        for (int nt = 0; nt < 8; nt++)
#pragma unroll
            for (int j = 0; j < 4; j++) {
                float p = exp2f(sc[nt][j] - ((j >> 1) ? mtot1 : mtot0));
                sc[nt][j] = p;
                rs[j >> 1] += p;
            }
#pragma unroll
        for (int off = 1; off < 4; off <<= 1) {
            rs[0] += __shfl_xor_sync(0xffffffffu, rs[0], off);
            rs[1] += __shfl_xor_sync(0xffffffffu, rs[1], off);
        }
        lrow[0] = lrow[0] * alpha0 + rs[0];
        lrow[1] = lrow[1] * alpha1 + rs[1];

#pragma unroll
        for (int nt = 0; nt < 16; nt++) {
            acc[nt][0] *= alpha0; acc[nt][1] *= alpha0;
            acc[nt][2] *= alpha1; acc[nt][3] *= alpha1;
        }

        // P -> smem (per-warp private), rna-rounded
        float* Pw = Ps + warp * 16 * APS;
#pragma unroll
        for (int nt = 0; nt < 8; nt++)
#pragma unroll
            for (int j = 0; j < 4; j++) {
                int row = lr + (j >> 1) * 8;
                int col = nt * 8 + lc * 2 + (j & 1);
                Pw[row * APS + col] = __uint_as_float(to_tf32(sc[nt][j]));
            }
        __syncwarp();

        // ---- O += P @ V (1xTF32) ----
#pragma unroll
        for (int ks2 = 0; ks2 < 8; ks2++) {
            uint32_t pa[4];
            pa[0] = __float_as_uint(Pw[lr * APS + ks2 * 8 + lc]);
            pa[1] = __float_as_uint(Pw[(lr + 8) * APS + ks2 * 8 + lc]);
            pa[2] = __float_as_uint(Pw[lr * APS + ks2 * 8 + lc + 4]);
            pa[3] = __float_as_uint(Pw[(lr + 8) * APS + ks2 * 8 + lc + 4]);
#pragma unroll
            for (int nt2 = 0; nt2 < 16; nt2++) {
                uint32_t vb[2];
                vb[0] = __float_as_uint(Vs[(ks2 * 8 + lc) * AVS + nt2 * 8 + lr]);
                vb[1] = __float_as_uint(Vs[(ks2 * 8 + lc + 4) * AVS + nt2 * 8 + lr]);
                mma_tf32(acc[nt2], pa, vb);
            }
        }
    }

    // Epilogue
    float inv0 = 1.f / lrow[0];
    float inv1 = 1.f / lrow[1];
    size_t obase = ((size_t)b * S_LEN + qrow0) * H_DIM;
#pragma unroll
    for (int nt2 = 0; nt2 < 16; nt2++) {
        int col = nt2 * 8 + lc * 2;
        *(float2*)(out + obase + col) =
            make_float2(acc[nt2][0] * inv0, acc[nt2][1] * inv0);
        *(float2*)(out + obase + (size_t)8 * H_DIM + col) =
            make_float2(acc[nt2][2] * inv1, acc[nt2][3] * inv1);
    }
}

// ---------------- launch ----------------

extern "C" void kernel_launch(void* const* d_in, const int* in_sizes, int n_in,
                              void* d_out, int out_size) {
    const float* x     = (const float*)d_in[0];
    const float* w_dkv = (const float*)d_in[1];
    const float* w_k   = (const float*)d_in[2];
    const float* w_v   = (const float*)d_in[3];
    const float* w_q   = (const float*)d_in[4];

    float* out = (float*)d_out;                          // [B,S,HEAD]
    float* latent = out + (size_t)M_TOTAL * H_DIM;       // [B,S,LATENT]

    float *qp, *kp, *vp, *wr;
    cudaGetSymbolAddress((void**)&qp, g_q);
    cudaGetSymbolAddress((void**)&kp, g_k);
    cudaGetSymbolAddress((void**)&vp, g_v);
    cudaGetSymbolAddress((void**)&wr, g_wr);

    constexpr int SMEM1 = 3 * (64 * 36 + 32 * (96 + 8)) * 4;   // 67584
    constexpr int SMEM2 = 3 * (64 * 36 + 32 * (64 + 8)) * 4;   // 55296

    static bool attrs_set = false;
    if (!attrs_set) {
        cudaFuncSetAttribute(gemm_kernel<96>,
                             cudaFuncAttributeMaxDynamicSharedMemorySize, SMEM1);
        cudaFuncSetAttribute(gemm_kernel<64>,
                             cudaFuncAttributeMaxDynamicSharedMemorySize, SMEM2);
        cudaFuncSetAttribute(attn_kernel,
                             cudaFuncAttributeMaxDynamicSharedMemorySize, ATTN_SMEM_BYTES);
        attrs_set = true;
    }

    // 0) pre-round all weights to tf32-rna (unbiased)
    prep_w<<<WR_TOT / 256, 256>>>(w_dkv, w_q, w_k, w_v);

    // 1) latent = x@w_dkv -> d_out latent region; q = x@w_q -> scratch (fp32 out)
    //    grid (n,m): 2 n-blocks sharing one x tile are adjacent -> L2 reuse
    gemm_kernel<96><<<dim3(2, M_TOTAL / 64), 256, SMEM1>>>(
        x, wr + WR_DKV, wr + WR_Q, latent, qp, E_DIM, L_DIM, H_DIM, 0);

    // 2) k = latent@w_k, v = latent@w_v -> scratch, rna-rounded on store
    gemm_kernel<64><<<dim3(4, M_TOTAL / 64), 256, SMEM2>>>(
        latent, wr + WR_K, wr + WR_V, kp, vp, L_DIM, H_DIM, H_DIM, 1);

    // 3) causal flash attention (R5 geometry: 512 CTAs, 2/SM, longest-first)
    attn_kernel<<<512, 128, ATTN_SMEM_BYTES>>>(qp, kp, vp, out);
}

// round 8
// speedup vs baseline: 1.6372x; 1.4232x over previous
#include <cuda_runtime.h>
#include <cstdint>

#define M_TOTAL 32768
#define E_DIM 2048
#define L_DIM 64
#define H_DIM 128
#define S_LEN 4096

// Scratch (device globals: allocation-free rule)
__device__ float g_q[(size_t)M_TOTAL * H_DIM];
__device__ float g_k[(size_t)M_TOTAL * H_DIM];
__device__ float g_v[(size_t)M_TOTAL * H_DIM];

// Pre-rounded (tf32-rna) weights, same layouts as inputs:
// [w_dkv (2048x64) | w_q (2048x128) | w_k (64x128) | w_v (64x128)]
#define WR_DKV 0
#define WR_Q   (2048 * 64)
#define WR_K   (WR_Q + 2048 * 128)
#define WR_V   (WR_K + 64 * 128)
#define WR_TOT (WR_V + 64 * 128)
__device__ float g_wr[WR_TOT];

// ---------------- tf32 / async helpers ----------------

__device__ __forceinline__ void mma_tf32(float* d, const uint32_t* a, const uint32_t* b) {
    asm volatile(
        "mma.sync.aligned.m16n8k8.row.col.f32.tf32.tf32.f32 "
        "{%0,%1,%2,%3}, {%4,%5,%6,%7}, {%8,%9}, {%0,%1,%2,%3};\n"
        : "+f"(d[0]), "+f"(d[1]), "+f"(d[2]), "+f"(d[3])
        : "r"(a[0]), "r"(a[1]), "r"(a[2]), "r"(a[3]), "r"(b[0]), "r"(b[1]));
}

__device__ __forceinline__ uint32_t to_tf32(float x) {
    uint32_t h;
    asm("cvt.rna.tf32.f32 %0, %1;" : "=r"(h) : "f"(x));
    return h;
}

__device__ __forceinline__ void cp16(void* dst, const void* src) {
    uint32_t d = (uint32_t)__cvta_generic_to_shared(dst);
    asm volatile("cp.async.cg.shared.global [%0], [%1], 16;\n" :: "r"(d), "l"(src));
}
#define CP_COMMIT asm volatile("cp.async.commit_group;\n")
#define CP_WAIT0  asm volatile("cp.async.wait_group 0;\n")
#define CP_WAIT1  asm volatile("cp.async.wait_group 1;\n")
#define CP_WAIT2  asm volatile("cp.async.wait_group 2;\n")

// ---------------- weight pre-rounding (once per call, ~5us) ----------------

__global__ void prep_w(const float* __restrict__ w_dkv, const float* __restrict__ w_q,
                       const float* __restrict__ w_k, const float* __restrict__ w_v) {
    int i = blockIdx.x * 256 + threadIdx.x;
    float v;
    if (i < WR_Q)       v = w_dkv[i];
    else if (i < WR_K)  v = w_q[i - WR_Q];
    else if (i < WR_V)  v = w_k[i - WR_K];
    else                v = w_v[i - WR_V];
    g_wr[i] = __uint_as_float(to_tf32(v));
}

// ---------------- 3-stage pipelined 1xTF32 GEMM ----------------
// C = A[M,K] @ concat(B1[K,N1], B2[K,N2]); B pre-rounded tf32 in gmem;
// A rna-rounded at fragment load (1 cvt per element, no split, 1 MMA per tile).
// BM=64, KT=32, 256 threads = 8 warps as 2(m) x 4(n), 3 CTAs/SM.

template <int BN>
__global__ void __launch_bounds__(256, 3) gemm_kernel(
    const float* __restrict__ A,
    const float* __restrict__ B1, const float* __restrict__ B2,
    float* __restrict__ C1, float* __restrict__ C2,
    int K, int N1, int N2, int round_c)
{
    constexpr int BM = 64;
    constexpr int KTL = 32;
    constexpr int WNT = BN / 32;
    constexpr int ASTR = KTL + 4;           // 36
    constexpr int BSTR = BN + 8;
    constexpr int ASZ = BM * ASTR;
    constexpr int BSZ = KTL * BSTR;
    constexpr int BUF = ASZ + BSZ;

    extern __shared__ float sh[];

    const int tid = threadIdx.x;
    const int warp = tid >> 5, lane = tid & 31;
    const int wm = warp >> 2;
    const int wn = warp & 3;
    const int lr = lane >> 2, lc = lane & 3;
    const int m0 = blockIdx.y * BM;
    const int n0 = blockIdx.x * BN;

    const int arow = tid >> 2;              // 0..63
    const int ac4 = (tid & 3) * 4;          // 0,4,8,12 (+16)

    float acc[2][WNT][4];
#pragma unroll
    for (int mt = 0; mt < 2; mt++)
#pragma unroll
        for (int nt = 0; nt < WNT; nt++)
#pragma unroll
            for (int j = 0; j < 4; j++) acc[mt][nt][j] = 0.f;

    const int nk = K / KTL;

    auto stage = [&](int kt) {
        float* As = sh + (kt % 3) * BUF;
        float* Bs = As + ASZ;
        int kb = kt * KTL;
        cp16(&As[arow * ASTR + ac4],      A + (size_t)(m0 + arow) * K + kb + ac4);
        cp16(&As[arow * ASTR + ac4 + 16], A + (size_t)(m0 + arow) * K + kb + ac4 + 16);
        constexpr int NB = (KTL * BN / 4) / 256;
#pragma unroll
        for (int it = 0; it < NB; it++) {
            int i = it * 256 + tid;
            int brow = i / (BN / 4);
            int bc4 = (i % (BN / 4)) * 4;
            int gc = n0 + bc4;
            const float* src = (gc < N1) ? (B1 + (size_t)(kb + brow) * N1 + gc)
                                         : (B2 + (size_t)(kb + brow) * N2 + (gc - N1));
            cp16(&Bs[brow * BSTR + bc4], src);
        }
        CP_COMMIT;
    };

    stage(0);
    if (nk > 1) stage(1);

    for (int kt = 0; kt < nk; kt++) {
        if (kt + 2 < nk) { stage(kt + 2); CP_WAIT2; }
        else if (kt + 1 < nk) CP_WAIT1;
        else CP_WAIT0;
        __syncthreads();

        const float* As = sh + (kt % 3) * BUF;
        const float* Bs = As + ASZ;

#pragma unroll
        for (int ks = 0; ks < 4; ks++) {
            uint32_t ah[2][4];
#pragma unroll
            for (int mt = 0; mt < 2; mt++) {
                int rb = wm * 32 + mt * 16;
                ah[mt][0] = to_tf32(As[(rb + lr) * ASTR + ks * 8 + lc]);
                ah[mt][1] = to_tf32(As[(rb + lr + 8) * ASTR + ks * 8 + lc]);
                ah[mt][2] = to_tf32(As[(rb + lr) * ASTR + ks * 8 + lc + 4]);
                ah[mt][3] = to_tf32(As[(rb + lr + 8) * ASTR + ks * 8 + lc + 4]);
            }
#pragma unroll
            for (int nt = 0; nt < WNT; nt++) {
                int c0 = wn * (BN / 4) + nt * 8 + lr;
                uint32_t bh[2];
                bh[0] = __float_as_uint(Bs[(ks * 8 + lc) * BSTR + c0]);
                bh[1] = __float_as_uint(Bs[(ks * 8 + lc + 4) * BSTR + c0]);
#pragma unroll
                for (int mt = 0; mt < 2; mt++)
                    mma_tf32(acc[mt][nt], ah[mt], bh);
            }
        }
        __syncthreads();
    }

    // Store (optionally rna-rounded: k/v so attention's HW truncation is exact)
#pragma unroll
    for (int mt = 0; mt < 2; mt++) {
        int r0 = m0 + wm * 32 + mt * 16 + lr;
#pragma unroll
        for (int nt = 0; nt < WNT; nt++) {
            int gc = n0 + wn * (BN / 4) + nt * 8 + lc * 2;
            float* dst;
            int stride, col;
            if (gc < N1) { dst = C1; stride = N1; col = gc; }
            else         { dst = C2; stride = N2; col = gc - N1; }
            float o0 = acc[mt][nt][0], o1 = acc[mt][nt][1];
            float o2 = acc[mt][nt][2], o3 = acc[mt][nt][3];
            if (round_c) {
                o0 = __uint_as_float(to_tf32(o0));
                o1 = __uint_as_float(to_tf32(o1));
                o2 = __uint_as_float(to_tf32(o2));
                o3 = __uint_as_float(to_tf32(o3));
            }
            *(float2*)(dst + (size_t)r0 * stride + col)       = make_float2(o0, o1);
            *(float2*)(dst + (size_t)(r0 + 8) * stride + col) = make_float2(o2, o3);
        }
    }
}

// ---------------- Flash attention (causal) ----------------
// BLOCK_M=64 (4 warps x 16 rows), BLOCK_N=64, HEAD=128, 128 threads, 2 CTA/SM.
// QK^T: 1xTF32 (q rna-rounded in regs; K tf32-rna from gemm2).
// PV: 1xTF32 (P rna; V tf32-rna). Softmax in exp2 domain.

constexpr int AKS = 132;
constexpr int AVS = 136;
constexpr int APS = 68;
constexpr int ATTN_SMEM_BYTES = (64 * AKS + 64 * AVS + 64 * APS) * 4;  // 86016

__global__ void __launch_bounds__(128, 2) attn_kernel(
    const float* __restrict__ q, const float* __restrict__ k,
    const float* __restrict__ v, float* __restrict__ out)
{
    extern __shared__ float sm[];
    float* Ks = sm;
    float* Vs = sm + 64 * AKS;
    float* Ps = Vs + 64 * AVS;

    const int idx = blockIdx.x;
    const int b = idx & 7;
    const int qb = 63 - (idx >> 3);         // longest first
    const int tid = threadIdx.x;
    const int warp = tid >> 5, lane = tid & 31;
    const int lr = lane >> 2, lc = lane & 3;

    const float* qB = q + (size_t)b * S_LEN * H_DIM;
    const float* kB = k + (size_t)b * S_LEN * H_DIM;
    const float* vB = v + (size_t)b * S_LEN * H_DIM;

    const int qrow0 = qb * 64 + warp * 16 + lr;
    // 1/sqrt(128) * log2(e): scores in log2 domain -> exp2 softmax
    const float SCALE = 0.08838834764831845f * 1.4426950408889634f;

    // q fragments rna-rounded to tf32, kept in registers (64 regs)
    uint32_t qr[64];
#pragma unroll
    for (int ks = 0; ks < 16; ks++) {
        int c = ks * 8 + lc;
        qr[ks * 4 + 0] = to_tf32(qB[(size_t)qrow0 * H_DIM + c] * SCALE);
        qr[ks * 4 + 1] = to_tf32(qB[(size_t)(qrow0 + 8) * H_DIM + c] * SCALE);
        qr[ks * 4 + 2] = to_tf32(qB[(size_t)qrow0 * H_DIM + c + 4] * SCALE);
        qr[ks * 4 + 3] = to_tf32(qB[(size_t)(qrow0 + 8) * H_DIM + c + 4] * SCALE);
    }

    float acc[16][4];
#pragma unroll
    for (int nt = 0; nt < 16; nt++)
#pragma unroll
        for (int j = 0; j < 4; j++) acc[nt][j] = 0.f;
    float mrow[2] = {-INFINITY, -INFINITY};
    float lrow[2] = {0.f, 0.f};

    const int row64 = tid >> 5;
    const int c4 = (tid & 31) * 4;

    for (int kv = 0; kv <= qb; kv++) {
        __syncthreads();  // previous tile's readers done before overwrite

        // cp.async K,V tiles (64x128 each); values already tf32-rna from gemm2
#pragma unroll
        for (int rnd = 0; rnd < 16; rnd++) {
            int row = row64 + rnd * 4;
            cp16(&Ks[row * AKS + c4], kB + (size_t)(kv * 64 + row) * H_DIM + c4);
            cp16(&Vs[row * AVS + c4], vB + (size_t)(kv * 64 + row) * H_DIM + c4);
        }
        CP_COMMIT;
        CP_WAIT0;
        __syncthreads();

        // ---- S = q @ k^T (1xTF32) ----
        float sc[8][4];
#pragma unroll
        for (int nt = 0; nt < 8; nt++)
#pragma unroll
            for (int j = 0; j < 4; j++) sc[nt][j] = 0.f;

#pragma unroll
        for (int ks = 0; ks < 16; ks++) {
#pragma unroll
            for (int nt = 0; nt < 8; nt++) {
                uint32_t bh[2];
                bh[0] = __float_as_uint(Ks[(nt * 8 + lr) * AKS + ks * 8 + lc]);
                bh[1] = __float_as_uint(Ks[(nt * 8 + lr) * AKS + ks * 8 + lc + 4]);
                mma_tf32(sc[nt], &qr[ks * 4], bh);
            }
        }

        // Diagonal-block causal mask
        if (kv == qb) {
#pragma unroll
            for (int nt = 0; nt < 8; nt++)
#pragma unroll
                for (int j = 0; j < 4; j++) {
                    int col = nt * 8 + lc * 2 + (j & 1);
                    int row = warp * 16 + lr + (j >> 1) * 8;
                    if (col > row) sc[nt][j] = -INFINITY;
                }
        }

        // ---- online softmax (exp2 domain) ----
        float mnew[2] = {-INFINITY, -INFINITY};
#pragma unroll
        for (int nt = 0; nt < 8; nt++)
#pragma unroll
            for (int j = 0; j < 4; j++) mnew[j >> 1] = fmaxf(mnew[j >> 1], sc[nt][j]);
#pragma unroll
        for (int off = 1; off < 4; off <<= 1) {
            mnew[0] = fmaxf(mnew[0], __shfl_xor_sync(0xffffffffu, mnew[0], off));
            mnew[1] = fmaxf(mnew[1], __shfl_xor_sync(0xffffffffu, mnew[1], off));
        }
        float mtot0 = fmaxf(mrow[0], mnew[0]);
        float mtot1 = fmaxf(mrow[1], mnew[1]);
        float alpha0 = exp2f(mrow[0] - mtot0);
        float alpha1 = exp2f(mrow[1] - mtot1);
        mrow[0] = mtot0; mrow[1] = mtot1;

        float rs[2] = {0.f, 0.f};
#pragma unroll
        for (int nt = 0; nt < 8; nt++)
#pragma unroll
            for (int j = 0; j < 4; j++) {
                float p = exp2f(sc[nt][j] - ((j >> 1) ? mtot1 : mtot0));
                sc[nt][j] = p;
                rs[j >> 1] += p;
            }
#pragma unroll
        for (int off = 1; off < 4; off <<= 1) {
            rs[0] += __shfl_xor_sync(0xffffffffu, rs[0], off);
            rs[1] += __shfl_xor_sync(0xffffffffu, rs[1], off);
        }
        lrow[0] = lrow[0] * alpha0 + rs[0];
        lrow[1] = lrow[1] * alpha1 + rs[1];

#pragma unroll
        for (int nt = 0; nt < 16; nt++) {
            acc[nt][0] *= alpha0; acc[nt][1] *= alpha0;
            acc[nt][2] *= alpha1; acc[nt][3] *= alpha1;
        }

        // P -> smem (per-warp private), rna-rounded
        float* Pw = Ps + warp * 16 * APS;
#pragma unroll
        for (int nt = 0; nt < 8; nt++)
#pragma unroll
            for (int j = 0; j < 4; j++) {
                int row = lr + (j >> 1) * 8;
                int col = nt * 8 + lc * 2 + (j & 1);
                Pw[row * APS + col] = __uint_as_float(to_tf32(sc[nt][j]));
            }
        __syncwarp();

        // ---- O += P @ V (1xTF32) ----
#pragma unroll
        for (int ks2 = 0; ks2 < 8; ks2++) {
            uint32_t pa[4];
            pa[0] = __float_as_uint(Pw[lr * APS + ks2 * 8 + lc]);
            pa[1] = __float_as_uint(Pw[(lr + 8) * APS + ks2 * 8 + lc]);
            pa[2] = __float_as_uint(Pw[lr * APS + ks2 * 8 + lc + 4]);
            pa[3] = __float_as_uint(Pw[(lr + 8) * APS + ks2 * 8 + lc + 4]);
#pragma unroll
            for (int nt2 = 0; nt2 < 16; nt2++) {
                uint32_t vb[2];
                vb[0] = __float_as_uint(Vs[(ks2 * 8 + lc) * AVS + nt2 * 8 + lr]);
                vb[1] = __float_as_uint(Vs[(ks2 * 8 + lc + 4) * AVS + nt2 * 8 + lr]);
                mma_tf32(acc[nt2], pa, vb);
            }
        }
    }

    // Epilogue
    float inv0 = 1.f / lrow[0];
    float inv1 = 1.f / lrow[1];
    size_t obase = ((size_t)b * S_LEN + qrow0) * H_DIM;
#pragma unroll
    for (int nt2 = 0; nt2 < 16; nt2++) {
        int col = nt2 * 8 + lc * 2;
        *(float2*)(out + obase + col) =
            make_float2(acc[nt2][0] * inv0, acc[nt2][1] * inv0);
        *(float2*)(out + obase + (size_t)8 * H_DIM + col) =
            make_float2(acc[nt2][2] * inv1, acc[nt2][3] * inv1);
    }
}

// ---------------- launch ----------------

extern "C" void kernel_launch(void* const* d_in, const int* in_sizes, int n_in,
                              void* d_out, int out_size) {
    const float* x     = (const float*)d_in[0];
    const float* w_dkv = (const float*)d_in[1];
    const float* w_k   = (const float*)d_in[2];
    const float* w_v   = (const float*)d_in[3];
    const float* w_q   = (const float*)d_in[4];

    float* out = (float*)d_out;                          // [B,S,HEAD]
    float* latent = out + (size_t)M_TOTAL * H_DIM;       // [B,S,LATENT]

    float *qp, *kp, *vp, *wr;
    cudaGetSymbolAddress((void**)&qp, g_q);
    cudaGetSymbolAddress((void**)&kp, g_k);
    cudaGetSymbolAddress((void**)&vp, g_v);
    cudaGetSymbolAddress((void**)&wr, g_wr);

    constexpr int SMEM1 = 3 * (64 * 36 + 32 * (96 + 8)) * 4;   // 67584
    constexpr int SMEM2 = 3 * (64 * 36 + 32 * (64 + 8)) * 4;   // 55296

    static bool attrs_set = false;
    if (!attrs_set) {
        cudaFuncSetAttribute(gemm_kernel<96>,
                             cudaFuncAttributeMaxDynamicSharedMemorySize, SMEM1);
        cudaFuncSetAttribute(gemm_kernel<64>,
                             cudaFuncAttributeMaxDynamicSharedMemorySize, SMEM2);
        cudaFuncSetAttribute(attn_kernel,
                             cudaFuncAttributeMaxDynamicSharedMemorySize, ATTN_SMEM_BYTES);
        attrs_set = true;
    }

    // 0) pre-round all weights to tf32-rna (unbiased)
    prep_w<<<WR_TOT / 256, 256>>>(w_dkv, w_q, w_k, w_v);

    // 1) latent = x@w_dkv -> d_out latent region; q = x@w_q -> scratch
    gemm_kernel<96><<<dim3(2, M_TOTAL / 64), 256, SMEM1>>>(
        x, wr + WR_DKV, wr + WR_Q, latent, qp, E_DIM, L_DIM, H_DIM, 0);

    // 2) k = latent@w_k, v = latent@w_v -> scratch, rna-rounded on store
    gemm_kernel<64><<<dim3(4, M_TOTAL / 64), 256, SMEM2>>>(
        latent, wr + WR_K, wr + WR_V, kp, vp, L_DIM, H_DIM, H_DIM, 1);

    // 3) causal flash attention (512 CTAs, 2/SM, longest-first)
    attn_kernel<<<512, 128, ATTN_SMEM_BYTES>>>(qp, kp, vp, out);
}

// round 9
// speedup vs baseline: 1.6494x; 1.0075x over previous
#include <cuda_runtime.h>
#include <cstdint>

#define M_TOTAL 32768
#define E_DIM 2048
#define L_DIM 64
#define H_DIM 128
#define S_LEN 4096

// Scratch (device globals: allocation-free rule)
__device__ float g_q[(size_t)M_TOTAL * H_DIM];
__device__ float g_k[(size_t)M_TOTAL * H_DIM];
__device__ float g_v[(size_t)M_TOTAL * H_DIM];

// Pre-rounded (tf32-rna) weights, same layouts as inputs:
#define WR_DKV 0
#define WR_Q   (2048 * 64)
#define WR_K   (WR_Q + 2048 * 128)
#define WR_V   (WR_K + 64 * 128)
#define WR_TOT (WR_V + 64 * 128)
__device__ float g_wr[WR_TOT];

// ---------------- tf32 / async helpers ----------------

__device__ __forceinline__ void mma_tf32(float* d, const uint32_t* a, const uint32_t* b) {
    asm volatile(
        "mma.sync.aligned.m16n8k8.row.col.f32.tf32.tf32.f32 "
        "{%0,%1,%2,%3}, {%4,%5,%6,%7}, {%8,%9}, {%0,%1,%2,%3};\n"
        : "+f"(d[0]), "+f"(d[1]), "+f"(d[2]), "+f"(d[3])
        : "r"(a[0]), "r"(a[1]), "r"(a[2]), "r"(a[3]), "r"(b[0]), "r"(b[1]));
}

__device__ __forceinline__ uint32_t to_tf32(float x) {
    uint32_t h;
    asm("cvt.rna.tf32.f32 %0, %1;" : "=r"(h) : "f"(x));
    return h;
}

__device__ __forceinline__ void cp16(void* dst, const void* src) {
    uint32_t d = (uint32_t)__cvta_generic_to_shared(dst);
    asm volatile("cp.async.cg.shared.global [%0], [%1], 16;\n" :: "r"(d), "l"(src));
}
#define CP_COMMIT asm volatile("cp.async.commit_group;\n")
#define CP_WAIT0  asm volatile("cp.async.wait_group 0;\n")
#define CP_WAIT1  asm volatile("cp.async.wait_group 1;\n")
#define CP_WAIT2  asm volatile("cp.async.wait_group 2;\n")

// ---------------- weight pre-rounding (once per call, ~5us) ----------------

__global__ void prep_w(const float* __restrict__ w_dkv, const float* __restrict__ w_q,
                       const float* __restrict__ w_k, const float* __restrict__ w_v) {
    int i = blockIdx.x * 256 + threadIdx.x;
    float v;
    if (i < WR_Q)       v = w_dkv[i];
    else if (i < WR_K)  v = w_q[i - WR_Q];
    else if (i < WR_V)  v = w_k[i - WR_K];
    else                v = w_v[i - WR_V];
    g_wr[i] = __uint_as_float(to_tf32(v));
}

// ---------------- 3-stage pipelined 1xTF32 GEMM ----------------
// C = A[M,K] @ concat(B1[K,N1], B2[K,N2]); B pre-rounded tf32 in gmem;
// A rna-rounded at fragment load. BM=64, KT=32, 256 threads = 8 warps 2(m)x4(n).
// round_c: rna-round outputs; C1 cols additionally scaled by c1s.

template <int BN>
__global__ void __launch_bounds__(256, 2) gemm_kernel(
    const float* __restrict__ A,
    const float* __restrict__ B1, const float* __restrict__ B2,
    float* __restrict__ C1, float* __restrict__ C2,
    int K, int N1, int N2, int round_c, float c1s)
{
    constexpr int BM = 64;
    constexpr int KTL = 32;
    constexpr int WNT = BN / 32;
    constexpr int ASTR = KTL + 4;           // 36
    constexpr int BSTR = BN + 8;
    constexpr int ASZ = BM * ASTR;
    constexpr int BSZ = KTL * BSTR;
    constexpr int BUF = ASZ + BSZ;

    extern __shared__ float sh[];

    const int tid = threadIdx.x;
    const int warp = tid >> 5, lane = tid & 31;
    const int wm = warp >> 2;
    const int wn = warp & 3;
    const int lr = lane >> 2, lc = lane & 3;
    const int m0 = blockIdx.y * BM;
    const int n0 = blockIdx.x * BN;

    const int arow = tid >> 2;              // 0..63
    const int ac4 = (tid & 3) * 4;          // 0,4,8,12 (+16)

    float acc[2][WNT][4];
#pragma unroll
    for (int mt = 0; mt < 2; mt++)
#pragma unroll
        for (int nt = 0; nt < WNT; nt++)
#pragma unroll
            for (int j = 0; j < 4; j++) acc[mt][nt][j] = 0.f;

    const int nk = K / KTL;

    auto stage = [&](int kt) {
        float* As = sh + (kt % 3) * BUF;
        float* Bs = As + ASZ;
        int kb = kt * KTL;
        cp16(&As[arow * ASTR + ac4],      A + (size_t)(m0 + arow) * K + kb + ac4);
        cp16(&As[arow * ASTR + ac4 + 16], A + (size_t)(m0 + arow) * K + kb + ac4 + 16);
        constexpr int NB = (KTL * BN / 4) / 256;
#pragma unroll
        for (int it = 0; it < NB; it++) {
            int i = it * 256 + tid;
            int brow = i / (BN / 4);
            int bc4 = (i % (BN / 4)) * 4;
            int gc = n0 + bc4;
            const float* src = (gc < N1) ? (B1 + (size_t)(kb + brow) * N1 + gc)
                                         : (B2 + (size_t)(kb + brow) * N2 + (gc - N1));
            cp16(&Bs[brow * BSTR + bc4], src);
        }
        CP_COMMIT;
    };

    stage(0);
    if (nk > 1) stage(1);

    for (int kt = 0; kt < nk; kt++) {
        if (kt + 2 < nk) { stage(kt + 2); CP_WAIT2; }
        else if (kt + 1 < nk) CP_WAIT1;
        else CP_WAIT0;
        __syncthreads();

        const float* As = sh + (kt % 3) * BUF;
        const float* Bs = As + ASZ;

#pragma unroll
        for (int ks = 0; ks < 4; ks++) {
            uint32_t ah[2][4];
#pragma unroll
            for (int mt = 0; mt < 2; mt++) {
                int rb = wm * 32 + mt * 16;
                ah[mt][0] = to_tf32(As[(rb + lr) * ASTR + ks * 8 + lc]);
                ah[mt][1] = to_tf32(As[(rb + lr + 8) * ASTR + ks * 8 + lc]);
                ah[mt][2] = to_tf32(As[(rb + lr) * ASTR + ks * 8 + lc + 4]);
                ah[mt][3] = to_tf32(As[(rb + lr + 8) * ASTR + ks * 8 + lc + 4]);
            }
#pragma unroll
            for (int nt = 0; nt < WNT; nt++) {
                int c0 = wn * (BN / 4) + nt * 8 + lr;
                uint32_t bh[2];
                bh[0] = __float_as_uint(Bs[(ks * 8 + lc) * BSTR + c0]);
                bh[1] = __float_as_uint(Bs[(ks * 8 + lc + 4) * BSTR + c0]);
#pragma unroll
                for (int mt = 0; mt < 2; mt++)
                    mma_tf32(acc[mt][nt], ah[mt], bh);
            }
        }
        __syncthreads();
    }

#pragma unroll
    for (int mt = 0; mt < 2; mt++) {
        int r0 = m0 + wm * 32 + mt * 16 + lr;
#pragma unroll
        for (int nt = 0; nt < WNT; nt++) {
            int gc = n0 + wn * (BN / 4) + nt * 8 + lc * 2;
            float* dst;
            int stride, col;
            float cs = 1.f;
            if (gc < N1) { dst = C1; stride = N1; col = gc; cs = c1s; }
            else         { dst = C2; stride = N2; col = gc - N1; }
            float o0 = acc[mt][nt][0], o1 = acc[mt][nt][1];
            float o2 = acc[mt][nt][2], o3 = acc[mt][nt][3];
            if (round_c) {
                o0 = __uint_as_float(to_tf32(o0 * cs));
                o1 = __uint_as_float(to_tf32(o1 * cs));
                o2 = __uint_as_float(to_tf32(o2 * cs));
                o3 = __uint_as_float(to_tf32(o3 * cs));
            }
            *(float2*)(dst + (size_t)r0 * stride + col)       = make_float2(o0, o1);
            *(float2*)(dst + (size_t)(r0 + 8) * stride + col) = make_float2(o2, o3);
        }
    }
}

// ---------------- Flash attention (causal), LDS-byte-optimized ----------------
// BLOCK_M=64, 4 warps = (wm: 32-row half) x (wn: 32-kv-col half for QK /
// 64-head-col half for PV). Each warp: QK 2mt x 4nt (K reads halved),
// PV 2mt x 8nt2 (V reads halved, B-frag reused). q mt0 in regs, mt1 from smem Q.
// P written into dead Ks region. Cross-warp softmax via smem exchange.
// k pre-scaled by 1/sqrt(128)*log2e in gemm2; softmax in exp2 domain.

constexpr int AKS = 132;
constexpr int AVS = 136;
constexpr int APS = 68;                 // P stride (aliased in Ks region)
constexpr int VOFF = 64 * AKS;          // 8448
constexpr int XOFF = VOFF + 64 * AVS;   // 17152 (exchange buffer, 128 floats)
constexpr int QOFF = XOFF + 128;        // 17280
constexpr int ATTN_SMEM_BYTES = (QOFF + 64 * 132) * 4;   // 102912

__global__ void __launch_bounds__(128, 2) attn_kernel(
    const float* __restrict__ q, const float* __restrict__ k,
    const float* __restrict__ v, float* __restrict__ out)
{
    extern __shared__ float sm[];
    float* Ks = sm;                 // K tile; later aliased as P (stride APS)
    float* Vs = sm + VOFF;
    float* Xb = sm + XOFF;
    float* Qs = sm + QOFF;

    const int idx = blockIdx.x;
    const int b = idx & 7;
    const int qb = 63 - (idx >> 3);         // longest first
    const int tid = threadIdx.x;
    const int warp = tid >> 5, lane = tid & 31;
    const int lr = lane >> 2, lc = lane & 3;
    const int wm = warp >> 1;               // row half (32 rows)
    const int wn = warp & 1;                // kv half (QK) / head half (PV)

    const float* qB = q + (size_t)b * S_LEN * H_DIM;
    const float* kB = k + (size_t)b * S_LEN * H_DIM;
    const float* vB = v + (size_t)b * S_LEN * H_DIM;

    const int row64 = tid >> 5;
    const int c4 = (tid & 31) * 4;

    // Stage Q tile (64 x 128) once
#pragma unroll
    for (int rnd = 0; rnd < 16; rnd++) {
        int row = row64 + rnd * 4;
        cp16(&Qs[row * 132 + c4], qB + (size_t)(qb * 64 + row) * H_DIM + c4);
    }
    CP_COMMIT;

    // q mt0 fragments (rows wm*32 + lr, +8) rna-rounded in regs
    const int qrow0 = qb * 64 + wm * 32 + lr;
    uint32_t qr[64];
#pragma unroll
    for (int ks = 0; ks < 16; ks++) {
        int c = ks * 8 + lc;
        qr[ks * 4 + 0] = to_tf32(qB[(size_t)qrow0 * H_DIM + c]);
        qr[ks * 4 + 1] = to_tf32(qB[(size_t)(qrow0 + 8) * H_DIM + c]);
        qr[ks * 4 + 2] = to_tf32(qB[(size_t)qrow0 * H_DIM + c + 4]);
        qr[ks * 4 + 3] = to_tf32(qB[(size_t)(qrow0 + 8) * H_DIM + c + 4]);
    }

    float acc[2][8][4];
#pragma unroll
    for (int mt = 0; mt < 2; mt++)
#pragma unroll
        for (int nt = 0; nt < 8; nt++)
#pragma unroll
            for (int j = 0; j < 4; j++) acc[mt][nt][j] = 0.f;
    float mrow[2][2] = {{-INFINITY, -INFINITY}, {-INFINITY, -INFINITY}};
    float lrow[2][2] = {{0.f, 0.f}, {0.f, 0.f}};

    for (int kv = 0; kv <= qb; kv++) {
        __syncthreads();  // (1) Ks(P)/Vs dead

        // stage K,V tile (64 x 128 each)
#pragma unroll
        for (int rnd = 0; rnd < 16; rnd++) {
            int row = row64 + rnd * 4;
            cp16(&Ks[row * AKS + c4], kB + (size_t)(kv * 64 + row) * H_DIM + c4);
            cp16(&Vs[row * AVS + c4], vB + (size_t)(kv * 64 + row) * H_DIM + c4);
        }
        CP_COMMIT;
        CP_WAIT0;
        __syncthreads();  // (2) tiles ready

        // ---- S = q @ k^T : warp covers rows 32*wm (2mt) x kv cols 32*wn (4nt) ----
        float sc[2][4][4];
#pragma unroll
        for (int mt = 0; mt < 2; mt++)
#pragma unroll
            for (int nt = 0; nt < 4; nt++)
#pragma unroll
                for (int j = 0; j < 4; j++) sc[mt][nt][j] = 0.f;

        const int q1row = wm * 32 + 16 + lr;
#pragma unroll
        for (int ks = 0; ks < 16; ks++) {
            uint32_t q1[4];
            q1[0] = to_tf32(Qs[q1row * 132 + ks * 8 + lc]);
            q1[1] = to_tf32(Qs[(q1row + 8) * 132 + ks * 8 + lc]);
            q1[2] = to_tf32(Qs[q1row * 132 + ks * 8 + lc + 4]);
            q1[3] = to_tf32(Qs[(q1row + 8) * 132 + ks * 8 + lc + 4]);
#pragma unroll
            for (int nt = 0; nt < 4; nt++) {
                int kr = wn * 32 + nt * 8 + lr;
                uint32_t bh[2];
                bh[0] = __float_as_uint(Ks[kr * AKS + ks * 8 + lc]);
                bh[1] = __float_as_uint(Ks[kr * AKS + ks * 8 + lc + 4]);
                mma_tf32(sc[0][nt], &qr[ks * 4], bh);
                mma_tf32(sc[1][nt], q1, bh);
            }
        }

        // Diagonal-block causal mask (tile-local coords; same tile offset)
        if (kv == qb) {
#pragma unroll
            for (int mt = 0; mt < 2; mt++)
#pragma unroll
                for (int nt = 0; nt < 4; nt++)
#pragma unroll
                    for (int j = 0; j < 4; j++) {
                        int col = wn * 32 + nt * 8 + lc * 2 + (j & 1);
                        int row = wm * 32 + mt * 16 + lr + (j >> 1) * 8;
                        if (col > row) sc[mt][nt][j] = -INFINITY;
                    }
        }

        // ---- online softmax (exp2 domain, cross-warp over wn) ----
        float mnew[2][2] = {{-INFINITY, -INFINITY}, {-INFINITY, -INFINITY}};
#pragma unroll
        for (int mt = 0; mt < 2; mt++)
#pragma unroll
            for (int nt = 0; nt < 4; nt++)
#pragma unroll
                for (int j = 0; j < 4; j++)
                    mnew[mt][j >> 1] = fmaxf(mnew[mt][j >> 1], sc[mt][nt][j]);
#pragma unroll
        for (int off = 1; off < 4; off <<= 1)
#pragma unroll
            for (int mt = 0; mt < 2; mt++) {
                mnew[mt][0] = fmaxf(mnew[mt][0], __shfl_xor_sync(0xffffffffu, mnew[mt][0], off));
                mnew[mt][1] = fmaxf(mnew[mt][1], __shfl_xor_sync(0xffffffffu, mnew[mt][1], off));
            }
        if (lc == 0) {
#pragma unroll
            for (int mt = 0; mt < 2; mt++)
#pragma unroll
                for (int h = 0; h < 2; h++)
                    Xb[((wm * 2 + wn) * 4 + mt * 2 + h) * 8 + lr] = mnew[mt][h];
        }
        __syncthreads();  // (3) m-exchange

        float alpha[2][2];
#pragma unroll
        for (int mt = 0; mt < 2; mt++)
#pragma unroll
            for (int h = 0; h < 2; h++) {
                float mo = Xb[((wm * 2 + (1 - wn)) * 4 + mt * 2 + h) * 8 + lr];
                float mt_ = fmaxf(fmaxf(mrow[mt][h], mnew[mt][h]), mo);
                alpha[mt][h] = exp2f(mrow[mt][h] - mt_);
                mrow[mt][h] = mt_;
            }

        float rs[2][2] = {{0.f, 0.f}, {0.f, 0.f}};
#pragma unroll
        for (int mt = 0; mt < 2; mt++)
#pragma unroll
            for (int nt = 0; nt < 4; nt++)
#pragma unroll
                for (int j = 0; j < 4; j++) {
                    float p = exp2f(sc[mt][nt][j] - mrow[mt][j >> 1]);
                    sc[mt][nt][j] = p;
                    rs[mt][j >> 1] += p;
                }
#pragma unroll
        for (int off = 1; off < 4; off <<= 1)
#pragma unroll
            for (int mt = 0; mt < 2; mt++) {
                rs[mt][0] += __shfl_xor_sync(0xffffffffu, rs[mt][0], off);
                rs[mt][1] += __shfl_xor_sync(0xffffffffu, rs[mt][1], off);
            }

        // write P (rna) into dead Ks region; write rs partials
#pragma unroll
        for (int mt = 0; mt < 2; mt++)
#pragma unroll
            for (int nt = 0; nt < 4; nt++)
#pragma unroll
                for (int j = 0; j < 4; j++) {
                    int row = wm * 32 + mt * 16 + lr + (j >> 1) * 8;
                    int col = wn * 32 + nt * 8 + lc * 2 + (j & 1);
                    Ks[row * APS + col] = __uint_as_float(to_tf32(sc[mt][nt][j]));
                }
        if (lc == 0) {
#pragma unroll
            for (int mt = 0; mt < 2; mt++)
#pragma unroll
                for (int h = 0; h < 2; h++)
                    Xb[64 + ((wm * 2 + wn) * 4 + mt * 2 + h) * 8 + lr] = rs[mt][h];
        }
        __syncthreads();  // (4) P + rs ready

#pragma unroll
        for (int mt = 0; mt < 2; mt++)
#pragma unroll
            for (int h = 0; h < 2; h++) {
                float ro = Xb[64 + ((wm * 2 + (1 - wn)) * 4 + mt * 2 + h) * 8 + lr];
                lrow[mt][h] = lrow[mt][h] * alpha[mt][h] + rs[mt][h] + ro;
            }

#pragma unroll
        for (int mt = 0; mt < 2; mt++)
#pragma unroll
            for (int nt = 0; nt < 8; nt++) {
                acc[mt][nt][0] *= alpha[mt][0]; acc[mt][nt][1] *= alpha[mt][0];
                acc[mt][nt][2] *= alpha[mt][1]; acc[mt][nt][3] *= alpha[mt][1];
            }

        // ---- O += P @ V : warp covers rows 32*wm (2mt) x head cols 64*wn (8nt2) ----
#pragma unroll
        for (int ks2 = 0; ks2 < 8; ks2++) {
            uint32_t pa[2][4];
#pragma unroll
            for (int mt = 0; mt < 2; mt++) {
                int base = wm * 32 + mt * 16;
                pa[mt][0] = __float_as_uint(Ks[(base + lr) * APS + ks2 * 8 + lc]);
                pa[mt][1] = __float_as_uint(Ks[(base + lr + 8) * APS + ks2 * 8 + lc]);
                pa[mt][2] = __float_as_uint(Ks[(base + lr) * APS + ks2 * 8 + lc + 4]);
                pa[mt][3] = __float_as_uint(Ks[(base + lr + 8) * APS + ks2 * 8 + lc + 4]);
            }
#pragma unroll
            for (int nt2 = 0; nt2 < 8; nt2++) {
                int vc = wn * 64 + nt2 * 8 + lr;
                uint32_t vb[2];
                vb[0] = __float_as_uint(Vs[(ks2 * 8 + lc) * AVS + vc]);
                vb[1] = __float_as_uint(Vs[(ks2 * 8 + lc + 4) * AVS + vc]);
                mma_tf32(acc[0][nt2], pa[0], vb);
                mma_tf32(acc[1][nt2], pa[1], vb);
            }
        }
    }

    // Epilogue: rows 32*wm + mt*16 + lr (+8), cols 64*wn + nt2*8 + 2lc (+1)
#pragma unroll
    for (int mt = 0; mt < 2; mt++) {
        float inv0 = 1.f / lrow[mt][0];
        float inv1 = 1.f / lrow[mt][1];
        size_t rowg = (size_t)b * S_LEN + qb * 64 + wm * 32 + mt * 16 + lr;
#pragma unroll
        for (int nt2 = 0; nt2 < 8; nt2++) {
            int col = wn * 64 + nt2 * 8 + lc * 2;
            *(float2*)(out + rowg * H_DIM + col) =
                make_float2(acc[mt][nt2][0] * inv0, acc[mt][nt2][1] * inv0);
            *(float2*)(out + (rowg + 8) * H_DIM + col) =
                make_float2(acc[mt][nt2][2] * inv1, acc[mt][nt2][3] * inv1);
        }
    }
}

// ---------------- launch ----------------

extern "C" void kernel_launch(void* const* d_in, const int* in_sizes, int n_in,
                              void* d_out, int out_size) {
    const float* x     = (const float*)d_in[0];
    const float* w_dkv = (const float*)d_in[1];
    const float* w_k   = (const float*)d_in[2];
    const float* w_v   = (const float*)d_in[3];
    const float* w_q   = (const float*)d_in[4];

    float* out = (float*)d_out;                          // [B,S,HEAD]
    float* latent = out + (size_t)M_TOTAL * H_DIM;       // [B,S,LATENT]

    float *qp, *kp, *vp, *wr;
    cudaGetSymbolAddress((void**)&qp, g_q);
    cudaGetSymbolAddress((void**)&kp, g_k);
    cudaGetSymbolAddress((void**)&vp, g_v);
    cudaGetSymbolAddress((void**)&wr, g_wr);

    constexpr int SMEM1 = 3 * (64 * 36 + 32 * (192 + 8)) * 4;  // 104448
    constexpr int SMEM2 = 3 * (64 * 36 + 32 * (128 + 8)) * 4;  // 79872

    static bool attrs_set = false;
    if (!attrs_set) {
        cudaFuncSetAttribute(gemm_kernel<192>,
                             cudaFuncAttributeMaxDynamicSharedMemorySize, SMEM1);
        cudaFuncSetAttribute(gemm_kernel<128>,
                             cudaFuncAttributeMaxDynamicSharedMemorySize, SMEM2);
        cudaFuncSetAttribute(attn_kernel,
                             cudaFuncAttributeMaxDynamicSharedMemorySize, ATTN_SMEM_BYTES);
        attrs_set = true;
    }

    // k scale folded into gemm2 epilogue: 1/sqrt(128) * log2(e)
    const float KSCALE = 0.08838834764831845f * 1.4426950408889634f;

    // 0) pre-round all weights to tf32-rna (unbiased)
    prep_w<<<WR_TOT / 256, 256>>>(w_dkv, w_q, w_k, w_v);

    // 1) latent = x@w_dkv -> d_out latent; q = x@w_q -> scratch (single n-block)
    gemm_kernel<192><<<dim3(1, M_TOTAL / 64), 256, SMEM1>>>(
        x, wr + WR_DKV, wr + WR_Q, latent, qp, E_DIM, L_DIM, H_DIM, 0, 1.f);

    // 2) k = latent@w_k (scaled), v = latent@w_v -> scratch, rna on store
    gemm_kernel<128><<<dim3(2, M_TOTAL / 64), 256, SMEM2>>>(
        latent, wr + WR_K, wr + WR_V, kp, vp, L_DIM, H_DIM, H_DIM, 1, KSCALE);

    // 3) causal flash attention (512 CTAs, 2/SM, longest-first)
    attn_kernel<<<512, 128, ATTN_SMEM_BYTES>>>(qp, kp, vp, out);
}